// round 14
// baseline (speedup 1.0000x reference)
#include <cuda_runtime.h>
#include <cstdint>

#define F 128
#define F4 (F/4)
#define MAX_ATOMS 20000
#define MAX_PAIRS 320000
#define SCAN_THREADS 1024
#define SCAN_PER ((MAX_ATOMS + SCAN_THREADS - 1) / SCAN_THREADS)   // 20

// GEMM tile config: 32 atoms/tile, 256 threads, thread = 6 rows x 8 cols,
// f-partial f32x2 accumulators (no operand duplication).
#define GA 32
#define GT 256
#define WROW 65          // u64 stride per W row (130 f32, 8B-aligned, conflict-free)
#define VROW 65          // u64 stride per V row

typedef unsigned long long u64;

// Scratch (allocation-free rule: __device__ globals; zero-init at load;
// g_cnt restored to zero by scan_kernel every run)
__device__ float4     g_V[MAX_ATOMS * 3 * F4];   // V[i][c][:] accumulators
__device__ int        g_cnt[MAX_ATOMS];          // hist counters (self-zeroing)
__device__ int        g_cnt2[MAX_ATOMS];         // stable copy of counts
__device__ int        g_off[MAX_ATOMS];          // bin offsets
__device__ int        g_pos[MAX_PAIRS];          // within-bin position
__device__ int        g_recJ[MAX_PAIRS];         // binned neighbor index
__device__ ulonglong4 g_recP[MAX_PAIRS];         // packed ((xc,xc),(yc,yc),(zc,zc),(c,c))

__device__ __forceinline__ u64 pack64(float a, float b) {
    u64 r; asm("mov.b64 %0, {%1, %2};" : "=l"(r) : "f"(a), "f"(b)); return r;
}
__device__ __forceinline__ float2 unpack64(u64 v) {
    float2 r; asm("mov.b64 {%0, %1}, %2;" : "=f"(r.x), "=f"(r.y) : "l"(v)); return r;
}
#define FMA2(acc, a, b) asm("fma.rn.f32x2 %0, %1, %2, %0;" : "+l"(acc) : "l"(a), "l"(b))

// ---------------------------------------------------------------------------
// K1: prep = histogram + within-bin positions (W transpose no longer needed)
// ---------------------------------------------------------------------------
__global__ void prep_kernel(const int* __restrict__ pl, int n_pairs) {
    int p = blockIdx.x * blockDim.x + threadIdx.x;
    if (p < n_pairs) g_pos[p] = atomicAdd(&g_cnt[pl[p]], 1);
}

// ---------------------------------------------------------------------------
// K2: exclusive scan g_cnt -> g_off; copy counts to g_cnt2; zero g_cnt
// ---------------------------------------------------------------------------
__global__ void scan_kernel(int n_atoms) {
    __shared__ int ssum[SCAN_THREADS];
    int t = threadIdx.x;
    int base = t * SCAN_PER;
    int local[SCAN_PER];
    int s = 0;
#pragma unroll
    for (int k = 0; k < SCAN_PER; k++) {
        int idx = base + k;
        int v = 0;
        if (idx < n_atoms) {
            v = g_cnt[idx];
            g_cnt[idx] = 0;
            g_cnt2[idx] = v;
        }
        local[k] = s;
        s += v;
    }
    ssum[t] = s;
    __syncthreads();
    for (int d = 1; d < SCAN_THREADS; d <<= 1) {
        int x = (t >= d) ? ssum[t - d] : 0;
        __syncthreads();
        ssum[t] += x;
        __syncthreads();
    }
    int excl = (t > 0) ? ssum[t - 1] : 0;
#pragma unroll
    for (int k = 0; k < SCAN_PER; k++) {
        int idx = base + k;
        if (idx < n_atoms) g_off[idx] = excl + local[k];
    }
}

// ---------------------------------------------------------------------------
// K3: scatter pairs into bins; PRE-SCALED, PRE-PACKED records (R13-proven)
// ---------------------------------------------------------------------------
__global__ void scatter_kernel(const int* __restrict__ pl,
                               const float* __restrict__ cut,
                               const float* __restrict__ rij,
                               int n_pairs) {
    int p = blockIdx.x * blockDim.x + threadIdx.x;
    if (p >= n_pairs) return;
    int   i = pl[p];
    int   j = pl[n_pairs + p];
    float c = cut[p];
    float r0 = rij[3 * p + 0];
    float r1 = rij[3 * p + 1];
    float r2 = rij[3 * p + 2];
    float s = rsqrtf(r0 * r0 + r1 * r1 + r2 * r2) * c;
    int pos = g_off[i] + g_pos[p];
    float xc = r0 * s, yc = r1 * s, zc = r2 * s;
    ulonglong4 rec;
    rec.x = pack64(xc, xc);
    rec.y = pack64(yc, yc);
    rec.z = pack64(zc, zc);
    rec.w = pack64(c, c);
    g_recJ[pos] = j;
    g_recP[pos] = rec;
}

// ---------------------------------------------------------------------------
// K4: gather (R13-proven, 29us measured). One warp per atom; prepacked
// records staged in smem; 8 FMA2 + 1 LDG.128 per pair; 3 blocks/SM.
// ---------------------------------------------------------------------------
struct Acc2 { u64 r0, r1, x0, x1, y0, y1, z0, z1; };

__device__ __forceinline__ void accP(const ulonglong4& u, const ulonglong2& a, Acc2& s) {
    FMA2(s.r0, u.w, a.x); FMA2(s.r1, u.w, a.y);
    FMA2(s.x0, u.x, a.x); FMA2(s.x1, u.x, a.y);
    FMA2(s.y0, u.y, a.x); FMA2(s.y1, u.y, a.y);
    FMA2(s.z0, u.z, a.x); FMA2(s.z1, u.z, a.y);
}

__global__ __launch_bounds__(256, 3)
void gather_kernel(const ulonglong2* __restrict__ A2,
                   float* __restrict__ out, int n_atoms) {
    __shared__ int        sJ[8][32];
    __shared__ ulonglong4 sP[8][32];

    int warp = threadIdx.x >> 5, lane = threadIdx.x & 31;
    int w = blockIdx.x * 8 + warp;
    if (w >= n_atoms) return;
    int n = g_cnt2[w];
    int base = g_off[w];

    Acc2 s = {};

    for (int c0 = 0; c0 < n; c0 += 32) {
        int m = n - c0; if (m > 32) m = 32;
        if (lane < m) {
            sJ[warp][lane] = g_recJ[base + c0 + lane];
            sP[warp][lane] = g_recP[base + c0 + lane];
        }
        __syncwarp();
        int k = 0;
        for (; k + 4 <= m; k += 4) {
            int j0 = sJ[warp][k + 0];
            int j1 = sJ[warp][k + 1];
            int j2 = sJ[warp][k + 2];
            int j3 = sJ[warp][k + 3];
            ulonglong2 a0 = __ldg(&A2[j0 * F4 + lane]);
            ulonglong2 a1 = __ldg(&A2[j1 * F4 + lane]);
            ulonglong2 a2 = __ldg(&A2[j2 * F4 + lane]);
            ulonglong2 a3 = __ldg(&A2[j3 * F4 + lane]);
            accP(sP[warp][k + 0], a0, s);
            accP(sP[warp][k + 1], a1, s);
            accP(sP[warp][k + 2], a2, s);
            accP(sP[warp][k + 3], a3, s);
        }
        for (; k < m; k++) {
            int j0 = sJ[warp][k];
            ulonglong2 a0 = __ldg(&A2[j0 * F4 + lane]);
            accP(sP[warp][k], a0, s);
        }
        __syncwarp();
    }

    float2 p0, p1;
    p0 = unpack64(s.r0); p1 = unpack64(s.r1);
    *(float4*)(out + w * (2 * F) + F + lane * 4) = make_float4(p0.x, p0.y, p1.x, p1.y);
    p0 = unpack64(s.x0); p1 = unpack64(s.x1);
    g_V[(w * 3 + 0) * F4 + lane] = make_float4(p0.x, p0.y, p1.x, p1.y);
    p0 = unpack64(s.y0); p1 = unpack64(s.y1);
    g_V[(w * 3 + 1) * F4 + lane] = make_float4(p0.x, p0.y, p1.x, p1.y);
    p0 = unpack64(s.z0); p1 = unpack64(s.z1);
    g_V[(w * 3 + 2) * F4 + lane] = make_float4(p0.x, p0.y, p1.x, p1.y);
}

// ---------------------------------------------------------------------------
// K5: fused GEMM + norm, f-partial accumulators.
// acc[r][c] = (sum over even f, sum over odd f) of V[row_r][f] * W[col_c][f];
// final = acc.x + acc.y. Operands are NATURAL u64 pairs (v_f, v_f+1) and
// (w_f, w_f+1) — W used row-major (no transpose), V staged as straight copy.
// Thread = (ga = t&15 -> atoms {ga, ga+16}, cg = t>>4 -> cols cg*8..+7).
// Per 2-f per thread: 14 LDS.64 + 48 FMA2  -> FMA-bound.
// ---------------------------------------------------------------------------
__global__ __launch_bounds__(GT, 1)
void gemm_norm_kernel(const float* __restrict__ Wm,
                      const float* __restrict__ bias,
                      float* __restrict__ out, int n_atoms) {
    extern __shared__ char smraw[];
    u64* Ws = (u64*)smraw;                // [128][WROW]  (W rows, natural)
    u64* Vs = Ws + F * WROW;              // [96][VROW]   (V rows, natural)

    int t = threadIdx.x;
    int ga = t & 15;
    int cg = t >> 4;
    int atom0 = blockIdx.x * GA;

    // stage W (row-major, as-is): 128 rows x 64 u64
    {
        const u64* Wg = (const u64*)Wm;
        for (int k = t; k < F * 64; k += GT) {
            int g = k >> 6, fh = k & 63;
            Ws[g * WROW + fh] = Wg[k];
        }
    }
    // stage V: straight copy of 96 contiguous rows from g_V
    {
        const u64* Vg = (const u64*)g_V + (size_t)atom0 * 3 * 64;
        int vmax = (n_atoms - atom0) * 3 * 64;
        for (int k = t; k < 96 * 64; k += GT) {
            int row = k >> 6, fh = k & 63;
            Vs[row * VROW + fh] = (k < vmax) ? Vg[k] : 0ULL;
        }
    }
    __syncthreads();

    u64 acc[6][8] = {};   // 6 rows (2 atoms x 3 channels) x 8 cols

#pragma unroll 2
    for (int fh = 0; fh < 64; fh++) {
        u64 wv[8];
#pragma unroll
        for (int c = 0; c < 8; c++)
            wv[c] = Ws[(cg * 8 + c) * WROW + fh];
        u64 vv[6];
#pragma unroll
        for (int r = 0; r < 6; r++) {
            int atom_l = (r < 3) ? ga : (ga + 16);
            vv[r] = Vs[(atom_l * 3 + (r % 3)) * VROW + fh];
        }
#pragma unroll
        for (int r = 0; r < 6; r++)
#pragma unroll
            for (int c = 0; c < 8; c++)
                FMA2(acc[r][c], vv[r], wv[c]);
    }

#pragma unroll
    for (int ha = 0; ha < 2; ha++) {
        int atom = atom0 + ga + ha * 16;
        if (atom >= n_atoms) continue;
        float cnt = (float)g_cnt2[atom];
        float4 bv0 = __ldg((const float4*)&bias[cg * 8]);
        float4 bv1 = __ldg((const float4*)&bias[cg * 8 + 4]);
        float bb[8], ob[8];
        bb[0] = bv0.x * cnt; bb[1] = bv0.y * cnt; bb[2] = bv0.z * cnt; bb[3] = bv0.w * cnt;
        bb[4] = bv1.x * cnt; bb[5] = bv1.y * cnt; bb[6] = bv1.z * cnt; bb[7] = bv1.w * cnt;
#pragma unroll
        for (int c = 0; c < 8; c++) {
            float2 px = unpack64(acc[ha * 3 + 0][c]);
            float2 py = unpack64(acc[ha * 3 + 1][c]);
            float2 pz = unpack64(acc[ha * 3 + 2][c]);
            float x = px.x + px.y + bb[c];
            float y = py.x + py.y + bb[c];
            float z = pz.x + pz.y + bb[c];
            ob[c] = sqrtf(x * x + y * y + z * z + 1e-12f);
        }
        float* o = &out[atom * (2 * F) + cg * 8];
        *(float4*)o       = make_float4(ob[0], ob[1], ob[2], ob[3]);
        *(float4*)(o + 4) = make_float4(ob[4], ob[5], ob[6], ob[7]);
    }
}

// ---------------------------------------------------------------------------
// Launch (5 kernels)
// ---------------------------------------------------------------------------
extern "C" void kernel_launch(void* const* d_in, const int* in_sizes, int n_in,
                              void* d_out, int out_size) {
    const float* A   = (const float*)d_in[0];   // [N, F]
    const int*   pl  = (const int*)  d_in[1];   // [2, P]
    const float* cut = (const float*)d_in[2];   // [P, 1]
    const float* rij = (const float*)d_in[3];   // [P, 3]
    const float* Wm  = (const float*)d_in[4];   // [F, F]
    const float* b   = (const float*)d_in[5];   // [F]
    float* out = (float*)d_out;                 // [N, 2F]

    int n_atoms = in_sizes[0] / F;
    int n_pairs = in_sizes[2];

    prep_kernel<<<(n_pairs + 255) / 256, 256>>>(pl, n_pairs);

    scan_kernel<<<1, SCAN_THREADS>>>(n_atoms);

    scatter_kernel<<<(n_pairs + 255) / 256, 256>>>(pl, cut, rij, n_pairs);

    gather_kernel<<<(n_atoms + 7) / 8, 256>>>((const ulonglong2*)A, out, n_atoms);

    {
        int smem = (F * WROW + 96 * VROW) * 8;   // (128+96)*65*8 = 116,480 B
        cudaFuncSetAttribute(gemm_norm_kernel,
                             cudaFuncAttributeMaxDynamicSharedMemorySize, smem);
        int grid = (n_atoms + GA - 1) / GA;      // 625
        gemm_norm_kernel<<<grid, GT, smem>>>(Wm, b, out, n_atoms);
    }
}

// round 15
// speedup vs baseline: 1.1878x; 1.1878x over previous
#include <cuda_runtime.h>
#include <cstdint>

#define F 128
#define F4 (F/4)
#define MAX_ATOMS 20000
#define MAX_PAIRS 320000
#define SCAN_THREADS 1024
#define SCAN_PER ((MAX_ATOMS + SCAN_THREADS - 1) / SCAN_THREADS)   // 20

#define FW 8                 // warps per fused block
#define WROW 65              // u64 stride per W row in smem

typedef unsigned long long u64;

// Scratch (allocation-free rule: __device__ globals; zero-init at load;
// g_cnt restored to zero by scan_kernel every run)
__device__ int        g_cnt[MAX_ATOMS];          // hist counters (self-zeroing)
__device__ int        g_cnt2[MAX_ATOMS];         // stable copy of counts
__device__ int        g_off[MAX_ATOMS];          // bin offsets
__device__ int        g_pos[MAX_PAIRS];          // within-bin position
__device__ int        g_recJ[MAX_PAIRS];         // binned neighbor index
__device__ ulonglong4 g_recP[MAX_PAIRS];         // packed ((xc,xc),(yc,yc),(zc,zc),(c,c))

__device__ __forceinline__ u64 pack64(float a, float b) {
    u64 r; asm("mov.b64 %0, {%1, %2};" : "=l"(r) : "f"(a), "f"(b)); return r;
}
__device__ __forceinline__ float2 unpack64(u64 v) {
    float2 r; asm("mov.b64 {%0, %1}, %2;" : "=f"(r.x), "=f"(r.y) : "l"(v)); return r;
}
#define FMA2(acc, a, b) asm("fma.rn.f32x2 %0, %1, %2, %0;" : "+l"(acc) : "l"(a), "l"(b))

// ---------------------------------------------------------------------------
// K1: prep = histogram + within-bin positions
// ---------------------------------------------------------------------------
__global__ void prep_kernel(const int* __restrict__ pl, int n_pairs) {
    int p = blockIdx.x * blockDim.x + threadIdx.x;
    if (p < n_pairs) g_pos[p] = atomicAdd(&g_cnt[pl[p]], 1);
}

// ---------------------------------------------------------------------------
// K2: exclusive scan g_cnt -> g_off; copy counts to g_cnt2; zero g_cnt
// ---------------------------------------------------------------------------
__global__ void scan_kernel(int n_atoms) {
    __shared__ int ssum[SCAN_THREADS];
    int t = threadIdx.x;
    int base = t * SCAN_PER;
    int local[SCAN_PER];
    int s = 0;
#pragma unroll
    for (int k = 0; k < SCAN_PER; k++) {
        int idx = base + k;
        int v = 0;
        if (idx < n_atoms) {
            v = g_cnt[idx];
            g_cnt[idx] = 0;
            g_cnt2[idx] = v;
        }
        local[k] = s;
        s += v;
    }
    ssum[t] = s;
    __syncthreads();
    for (int d = 1; d < SCAN_THREADS; d <<= 1) {
        int x = (t >= d) ? ssum[t - d] : 0;
        __syncthreads();
        ssum[t] += x;
        __syncthreads();
    }
    int excl = (t > 0) ? ssum[t - 1] : 0;
#pragma unroll
    for (int k = 0; k < SCAN_PER; k++) {
        int idx = base + k;
        if (idx < n_atoms) g_off[idx] = excl + local[k];
    }
}

// ---------------------------------------------------------------------------
// K3: scatter pairs into bins; PRE-SCALED, PRE-PACKED records (proven)
// ---------------------------------------------------------------------------
__global__ void scatter_kernel(const int* __restrict__ pl,
                               const float* __restrict__ cut,
                               const float* __restrict__ rij,
                               int n_pairs) {
    int p = blockIdx.x * blockDim.x + threadIdx.x;
    if (p >= n_pairs) return;
    int   i = pl[p];
    int   j = pl[n_pairs + p];
    float c = cut[p];
    float r0 = rij[3 * p + 0];
    float r1 = rij[3 * p + 1];
    float r2 = rij[3 * p + 2];
    float s = rsqrtf(r0 * r0 + r1 * r1 + r2 * r2) * c;
    int pos = g_off[i] + g_pos[p];
    float xc = r0 * s, yc = r1 * s, zc = r2 * s;
    ulonglong4 rec;
    rec.x = pack64(xc, xc);
    rec.y = pack64(yc, yc);
    rec.z = pack64(zc, zc);
    rec.w = pack64(c, c);
    g_recJ[pos] = j;
    g_recP[pos] = rec;
}

// ---------------------------------------------------------------------------
// K4: FUSED gather + GEMM + norm. One warp per atom (grid-stride).
// Phase 1 (proven gather body): accumulate radial (-> out) and V in regs.
// Phase 2: exchange V through per-warp smem (1.5KB), apply 128x128 linear
// layer in-warp (f-partial f32x2 accumulators, W rows from block smem),
// norm + bias epilogue, write out. NO global V traffic at all.
// ---------------------------------------------------------------------------
struct Acc2 { u64 r0, r1, x0, x1, y0, y1, z0, z1; };

__device__ __forceinline__ void accP(const ulonglong4& u, const ulonglong2& a, Acc2& s) {
    FMA2(s.r0, u.w, a.x); FMA2(s.r1, u.w, a.y);
    FMA2(s.x0, u.x, a.x); FMA2(s.x1, u.x, a.y);
    FMA2(s.y0, u.y, a.x); FMA2(s.y1, u.y, a.y);
    FMA2(s.z0, u.z, a.x); FMA2(s.z1, u.z, a.y);
}

__global__ __launch_bounds__(FW * 32, 2)
void fused_kernel(const ulonglong2* __restrict__ A2,
                  const float* __restrict__ Wm,
                  const float* __restrict__ bias,
                  float* __restrict__ out, int n_atoms) {
    extern __shared__ char smraw[];
    u64*        Ws  = (u64*)smraw;                       // [128][WROW]
    u64*        Vex = Ws + F * WROW;                     // [FW][192]
    int*        sJb = (int*)(Vex + FW * 192);            // [FW][32]
    ulonglong4* sPb = (ulonglong4*)(sJb + FW * 32);      // [FW][32]

    int t = threadIdx.x;
    int warp = t >> 5, lane = t & 31;

    // stage W rows (row-major, natural u64 pairs) once per block
    {
        const u64* Wg = (const u64*)Wm;
        for (int k = t; k < F * 64; k += FW * 32) {
            int g = k >> 6, fh = k & 63;
            Ws[g * WROW + fh] = Wg[k];
        }
    }
    __syncthreads();

    u64*        myV = Vex + warp * 192;
    int*        mJ  = sJb + warp * 32;
    ulonglong4* mP  = sPb + warp * 32;
    int wstride = gridDim.x * FW;

    for (int w = blockIdx.x * FW + warp; w < n_atoms; w += wstride) {
        int n = g_cnt2[w];
        int base = g_off[w];

        // ---- Phase 1: gather (R13-proven body) ----
        Acc2 s = {};
        for (int c0 = 0; c0 < n; c0 += 32) {
            int m = n - c0; if (m > 32) m = 32;
            if (lane < m) {
                mJ[lane] = g_recJ[base + c0 + lane];
                mP[lane] = g_recP[base + c0 + lane];
            }
            __syncwarp();
            int k = 0;
            for (; k + 4 <= m; k += 4) {
                int j0 = mJ[k + 0];
                int j1 = mJ[k + 1];
                int j2 = mJ[k + 2];
                int j3 = mJ[k + 3];
                ulonglong2 a0 = __ldg(&A2[j0 * F4 + lane]);
                ulonglong2 a1 = __ldg(&A2[j1 * F4 + lane]);
                ulonglong2 a2 = __ldg(&A2[j2 * F4 + lane]);
                ulonglong2 a3 = __ldg(&A2[j3 * F4 + lane]);
                accP(mP[k + 0], a0, s);
                accP(mP[k + 1], a1, s);
                accP(mP[k + 2], a2, s);
                accP(mP[k + 3], a3, s);
            }
            for (; k < m; k++) {
                int j0 = mJ[k];
                ulonglong2 a0 = __ldg(&A2[j0 * F4 + lane]);
                accP(mP[k], a0, s);
            }
            __syncwarp();
        }

        // radial half of output straight to gmem
        {
            float2 p0 = unpack64(s.r0), p1 = unpack64(s.r1);
            *(float4*)(out + w * (2 * F) + F + lane * 4) =
                make_float4(p0.x, p0.y, p1.x, p1.y);
        }

        // ---- exchange V through per-warp smem ----
        // lane l holds f = 4l..4l+3 per channel as two u64s
        {
            ulonglong2 q;
            q.x = s.x0; q.y = s.x1;
            *(ulonglong2*)&myV[0 * 64 + 2 * lane] = q;
            q.x = s.y0; q.y = s.y1;
            *(ulonglong2*)&myV[1 * 64 + 2 * lane] = q;
            q.x = s.z0; q.y = s.z1;
            *(ulonglong2*)&myV[2 * 64 + 2 * lane] = q;
        }
        __syncwarp();

        // ---- Phase 2: in-warp linear layer + norm ----
        // lane handles output cols g = lane + 32m, m=0..3
        u64 acc[3][4] = {};
#pragma unroll 4
        for (int fh = 0; fh < 64; fh++) {
            u64 v0 = myV[fh];
            u64 v1 = myV[64 + fh];
            u64 v2 = myV[128 + fh];
#pragma unroll
            for (int m = 0; m < 4; m++) {
                u64 wv = Ws[(lane + 32 * m) * WROW + fh];
                FMA2(acc[0][m], v0, wv);
                FMA2(acc[1][m], v1, wv);
                FMA2(acc[2][m], v2, wv);
            }
        }

        float cnt = (float)n;
#pragma unroll
        for (int m = 0; m < 4; m++) {
            int g = lane + 32 * m;
            float bb = __ldg(&bias[g]) * cnt;
            float2 px = unpack64(acc[0][m]);
            float2 py = unpack64(acc[1][m]);
            float2 pz = unpack64(acc[2][m]);
            float x = px.x + px.y + bb;
            float y = py.x + py.y + bb;
            float z = pz.x + pz.y + bb;
            out[w * (2 * F) + g] = sqrtf(x * x + y * y + z * z + 1e-12f);
        }
        __syncwarp();   // myV/mJ/mP safe to overwrite next iteration
    }
}

// ---------------------------------------------------------------------------
// Launch (4 kernels)
// ---------------------------------------------------------------------------
extern "C" void kernel_launch(void* const* d_in, const int* in_sizes, int n_in,
                              void* d_out, int out_size) {
    const float* A   = (const float*)d_in[0];   // [N, F]
    const int*   pl  = (const int*)  d_in[1];   // [2, P]
    const float* cut = (const float*)d_in[2];   // [P, 1]
    const float* rij = (const float*)d_in[3];   // [P, 3]
    const float* Wm  = (const float*)d_in[4];   // [F, F]
    const float* b   = (const float*)d_in[5];   // [F]
    float* out = (float*)d_out;                 // [N, 2F]

    int n_atoms = in_sizes[0] / F;
    int n_pairs = in_sizes[2];

    prep_kernel<<<(n_pairs + 255) / 256, 256>>>(pl, n_pairs);

    scan_kernel<<<1, SCAN_THREADS>>>(n_atoms);

    scatter_kernel<<<(n_pairs + 255) / 256, 256>>>(pl, cut, rij, n_pairs);

    {
        int smem = F * WROW * 8            // W: 66,560 B
                 + FW * 192 * 8            // V exchange: 12,288 B
                 + FW * 32 * 4             // sJ: 1,024 B
                 + FW * 32 * 32;           // sP: 8,192 B  -> 88,064 B total
        cudaFuncSetAttribute(fused_kernel,
                             cudaFuncAttributeMaxDynamicSharedMemorySize, smem);
        fused_kernel<<<296, FW * 32, smem>>>((const ulonglong2*)A, Wm, b, out, n_atoms);
    }
}